// round 15
// baseline (speedup 1.0000x reference)
#include <cuda_runtime.h>
#include <cuda_bf16.h>
#include <cuda_fp16.h>
#include <math.h>

#define BB 64
#define CC 512
#define KK 64
#define HW 4096
#define NSPLIT 4

#define AST 20     // logits W tile stride (u32)
#define BST 136    // logits X tile stride (u32)

#define AST2 12    // vlad A fp8 tile stride (u32): 64 rows x 8 u32 data
#define XRST 36    // vlad raw x8 tile stride (u32): 32 rows x 32 u32 data (144B, 16B-mult)
#define XTST 12    // vlad transposed tile stride (u32): 128 rows x 8 u32 data

// ---- scratch (device globals; no allocation allowed) ----
__device__ __align__(16) __nv_bfloat16 g_wb[KK * CC];
__device__ __align__(16) float         g_rnorm[BB * HW];
__device__ __align__(16) unsigned char g_x8[(size_t)BB * HW * CC];       // raw x e4m3, [b][i][c2]
__device__ __align__(16) unsigned char g_asg8[(size_t)BB * KK * HW];     // assign e4m3, [b][k][i]
__device__ __align__(16) float         g_asum_part[BB * KK * 32];
__device__ __align__(16) __nv_bfloat16 g_vpart[(size_t)NSPLIT * BB * KK * CC];
__device__ __align__(16) float         g_gss[BB * KK];

__device__ __forceinline__ void mma16816(float* d, const unsigned* a, const unsigned* b) {
    asm volatile(
        "mma.sync.aligned.m16n8k16.row.col.f32.bf16.bf16.f32 "
        "{%0,%1,%2,%3}, {%4,%5,%6,%7}, {%8,%9}, {%0,%1,%2,%3};"
        : "+f"(d[0]), "+f"(d[1]), "+f"(d[2]), "+f"(d[3])
        : "r"(a[0]), "r"(a[1]), "r"(a[2]), "r"(a[3]), "r"(b[0]), "r"(b[1]));
}

__device__ __forceinline__ void mma16832fp8(float* d, unsigned a0, unsigned a1,
                                            unsigned a2, unsigned a3,
                                            unsigned b0, unsigned b1) {
    asm volatile(
        "mma.sync.aligned.m16n8k32.row.col.f32.e4m3.e4m3.f32 "
        "{%0,%1,%2,%3}, {%4,%5,%6,%7}, {%8,%9}, {%0,%1,%2,%3};"
        : "+f"(d[0]), "+f"(d[1]), "+f"(d[2]), "+f"(d[3])
        : "r"(a0), "r"(a1), "r"(a2), "r"(a3), "r"(b0), "r"(b1));
}

__device__ __forceinline__ unsigned pack_bf2(float lo, float hi) {
    __nv_bfloat162 p = __floats2bfloat162_rn(lo, hi);
    return *reinterpret_cast<unsigned*>(&p);
}
__device__ __forceinline__ unsigned short pack_e4m3x2(float lo, float hi) {
    unsigned short r;
    asm("cvt.rn.satfinite.e4m3x2.f32 %0, %1, %2;" : "=h"(r) : "f"(hi), "f"(lo));
    return r;
}

__device__ __forceinline__ void cpasync16(unsigned* smem, const void* gmem) {
    unsigned s = (unsigned)__cvta_generic_to_shared(smem);
    asm volatile("cp.async.ca.shared.global [%0], [%1], 16;\n" :: "r"(s), "l"(gmem));
}
__device__ __forceinline__ void cp_commit() {
    asm volatile("cp.async.commit_group;\n");
}
__device__ __forceinline__ void cp_wait0() {
    asm volatile("cp.async.wait_group 0;\n");
}

// ---------------- K_pre ----------------
__global__ void k_pre(const float* __restrict__ w) {
    int t = blockIdx.x * 256 + threadIdx.x;
    if (t < KK * CC) g_wb[t] = __float2bfloat16(w[t]);
}

// ---------------- K2: norm + logits GEMM + softmax; also emit x8 / asg8 ------
// grid (HW/128, BB), 256 threads, K-chunk = 32 channels
__global__ __launch_bounds__(256) void k_logits(const float* __restrict__ x,
                                                const float* __restrict__ conv_b) {
    __shared__ __align__(16) unsigned smW[2 * KK * AST];
    __shared__ __align__(16) unsigned smX[2 * 16 * BST];
    __shared__ float rnorm_s[128];
    __shared__ float bias_s[KK];

    const int b  = blockIdx.y;
    const int bi = blockIdx.x;
    const int i0 = bi * 128;
    const int qq  = bi >> 2;           // i mod-8 class of this tile
    const int c2b = (bi & 3) * 128;    // xf column range base
    const int t  = threadIdx.x;
    const int lane = t & 31, warp = t >> 5;
    const int mw = warp >> 1, nw = warp & 1;
    const int g = lane >> 2, tg = lane & 3;

    if (t < KK) bias_s[t] = conv_b[t];

    const float* xb = x + (size_t)b * CC * HW + i0;
    const unsigned* wb32 = reinterpret_cast<const unsigned*>(g_wb);

    const int c4 = t & 31, cg = t >> 5;
    const int wrow = t >> 2, wq = t & 3;

    unsigned char* x8base = g_x8 + (size_t)b * HW * CC + c2b + c4 * 4;

    float acc[8][4];
#pragma unroll
    for (int nt = 0; nt < 8; nt++)
#pragma unroll
        for (int q = 0; q < 4; q++) acc[nt][q] = 0.f;
    float4 ssq4 = make_float4(0.f, 0.f, 0.f, 0.f);

    float4 xr[4];
    cpasync16(smW + wrow * AST + wq * 4, wb32 + wrow * (CC / 2) + wq * 4);
    cp_commit();
#pragma unroll
    for (int r = 0; r < 4; r++)
        xr[r] = *reinterpret_cast<const float4*>(xb + (size_t)(4 * cg + r) * HW + c4 * 4);
    {
        ssq4.x += xr[0].x * xr[0].x + xr[1].x * xr[1].x + xr[2].x * xr[2].x + xr[3].x * xr[3].x;
        ssq4.y += xr[0].y * xr[0].y + xr[1].y * xr[1].y + xr[2].y * xr[2].y + xr[3].y * xr[3].y;
        ssq4.z += xr[0].z * xr[0].z + xr[1].z * xr[1].z + xr[2].z * xr[2].z + xr[3].z * xr[3].z;
        ssq4.w += xr[0].w * xr[0].w + xr[1].w * xr[1].w + xr[2].w * xr[2].w + xr[3].w * xr[3].w;
        uint4 p0 = make_uint4(pack_bf2(xr[0].x, xr[1].x), pack_bf2(xr[0].y, xr[1].y),
                              pack_bf2(xr[0].z, xr[1].z), pack_bf2(xr[0].w, xr[1].w));
        uint4 p1 = make_uint4(pack_bf2(xr[2].x, xr[3].x), pack_bf2(xr[2].y, xr[3].y),
                              pack_bf2(xr[2].z, xr[3].z), pack_bf2(xr[2].w, xr[3].w));
        *reinterpret_cast<uint4*>(smX + (2 * cg) * BST + c4 * 4) = p0;
        *reinterpret_cast<uint4*>(smX + (2 * cg + 1) * BST + c4 * 4) = p1;
#pragma unroll
        for (int r = 0; r < 4; r++) {
            unsigned lo = pack_e4m3x2(xr[r].x, xr[r].y);
            unsigned hi = pack_e4m3x2(xr[r].z, xr[r].w);
            *reinterpret_cast<unsigned*>(
                x8base + (size_t)(8 * (4 * cg + r) + qq) * 512) = lo | (hi << 16);
        }
    }
    cp_wait0();
    __syncthreads();

    const int NIT = CC / 32;
    for (int it = 0; it < NIT; it++) {
        const int c1 = (it + 1) * 32;
        const int s = it & 1, sn = s ^ 1;
        if (it < NIT - 1) {
            cpasync16(smW + sn * (KK * AST) + wrow * AST + wq * 4,
                      wb32 + wrow * (CC / 2) + (c1 >> 1) + wq * 4);
            cp_commit();
#pragma unroll
            for (int r = 0; r < 4; r++)
                xr[r] = *reinterpret_cast<const float4*>(
                    xb + (size_t)(c1 + 4 * cg + r) * HW + c4 * 4);
        }

        const unsigned* Ws = smW + s * (KK * AST);
        const unsigned* Xs = smX + s * (16 * BST);
        const int row = mw * 16 + g;
#pragma unroll
        for (int ks = 0; ks < 2; ks++) {
            unsigned a[4];
            a[0] = Ws[row * AST + ks * 8 + tg];
            a[1] = Ws[(row + 8) * AST + ks * 8 + tg];
            a[2] = Ws[row * AST + ks * 8 + tg + 4];
            a[3] = Ws[(row + 8) * AST + ks * 8 + tg + 4];
#pragma unroll
            for (int nt = 0; nt < 8; nt++) {
                const int col = nw * 64 + nt * 8 + g;
                unsigned bf[2];
                bf[0] = Xs[(ks * 8 + tg) * BST + col];
                bf[1] = Xs[(ks * 8 + tg + 4) * BST + col];
                mma16816(acc[nt], a, bf);
            }
        }

        if (it < NIT - 1) {
            unsigned* Xn = smX + sn * (16 * BST);
            ssq4.x += xr[0].x * xr[0].x + xr[1].x * xr[1].x + xr[2].x * xr[2].x + xr[3].x * xr[3].x;
            ssq4.y += xr[0].y * xr[0].y + xr[1].y * xr[1].y + xr[2].y * xr[2].y + xr[3].y * xr[3].y;
            ssq4.z += xr[0].z * xr[0].z + xr[1].z * xr[1].z + xr[2].z * xr[2].z + xr[3].z * xr[3].z;
            ssq4.w += xr[0].w * xr[0].w + xr[1].w * xr[1].w + xr[2].w * xr[2].w + xr[3].w * xr[3].w;
            uint4 p0 = make_uint4(pack_bf2(xr[0].x, xr[1].x), pack_bf2(xr[0].y, xr[1].y),
                                  pack_bf2(xr[0].z, xr[1].z), pack_bf2(xr[0].w, xr[1].w));
            uint4 p1 = make_uint4(pack_bf2(xr[2].x, xr[3].x), pack_bf2(xr[2].y, xr[3].y),
                                  pack_bf2(xr[2].z, xr[3].z), pack_bf2(xr[2].w, xr[3].w));
            *reinterpret_cast<uint4*>(Xn + (2 * cg) * BST + c4 * 4) = p0;
            *reinterpret_cast<uint4*>(Xn + (2 * cg + 1) * BST + c4 * 4) = p1;
#pragma unroll
            for (int r = 0; r < 4; r++) {
                unsigned lo = pack_e4m3x2(xr[r].x, xr[r].y);
                unsigned hi = pack_e4m3x2(xr[r].z, xr[r].w);
                *reinterpret_cast<unsigned*>(
                    x8base + (size_t)(8 * (c1 + 4 * cg + r) + qq) * 512) = lo | (hi << 16);
            }
        }
        cp_wait0();
        __syncthreads();
    }

    // ---- ssq -> rnorm ----
    float4* ssq_sm = reinterpret_cast<float4*>(smW);
    ssq_sm[cg * 32 + c4] = ssq4;
    __syncthreads();
    if (t < 32) {
        float4 s = ssq_sm[t];
#pragma unroll
        for (int r = 1; r < 8; r++) {
            float4 u = ssq_sm[r * 32 + t];
            s.x += u.x; s.y += u.y; s.z += u.z; s.w += u.w;
        }
        float4 rn;
        rn.x = 1.f / fmaxf(sqrtf(s.x), 1e-12f);
        rn.y = 1.f / fmaxf(sqrtf(s.y), 1e-12f);
        rn.z = 1.f / fmaxf(sqrtf(s.z), 1e-12f);
        rn.w = 1.f / fmaxf(sqrtf(s.w), 1e-12f);
        reinterpret_cast<float4*>(rnorm_s)[t] = rn;
        *reinterpret_cast<float4*>(g_rnorm + (size_t)b * HW + i0 + t * 4) = rn;
    }
    __syncthreads();

    float* colmax4 = reinterpret_cast<float*>(smX);
    float* colsum4 = reinterpret_cast<float*>(smX) + 512;
    float* asum2   = reinterpret_cast<float*>(smX) + 1024;

    const int row = mw * 16 + g;
    const float b0v = bias_s[row], b1v = bias_s[row + 8];

#pragma unroll
    for (int nt = 0; nt < 8; nt++) {
        const int col = nw * 64 + nt * 8 + tg * 2;
        const float r0 = rnorm_s[col], r1 = rnorm_s[col + 1];
        acc[nt][0] = acc[nt][0] * r0 + b0v;
        acc[nt][1] = acc[nt][1] * r1 + b0v;
        acc[nt][2] = acc[nt][2] * r0 + b1v;
        acc[nt][3] = acc[nt][3] * r1 + b1v;
    }

    float mA[8], mB[8];
#pragma unroll
    for (int nt = 0; nt < 8; nt++) {
        mA[nt] = fmaxf(acc[nt][0], acc[nt][2]);
        mB[nt] = fmaxf(acc[nt][1], acc[nt][3]);
    }
#pragma unroll
    for (int off = 4; off < 32; off <<= 1) {
#pragma unroll
        for (int nt = 0; nt < 8; nt++) {
            mA[nt] = fmaxf(mA[nt], __shfl_xor_sync(0xffffffffu, mA[nt], off));
            mB[nt] = fmaxf(mB[nt], __shfl_xor_sync(0xffffffffu, mB[nt], off));
        }
    }
    if (g == 0) {
#pragma unroll
        for (int nt = 0; nt < 8; nt++) {
            const int col = nw * 64 + nt * 8 + tg * 2;
            colmax4[col * 4 + mw] = mA[nt];
            colmax4[(col + 1) * 4 + mw] = mB[nt];
        }
    }
    __syncthreads();

    float sA[8], sB[8];
#pragma unroll
    for (int nt = 0; nt < 8; nt++) {
        const int col = nw * 64 + nt * 8 + tg * 2;
        float4 c0 = *reinterpret_cast<float4*>(colmax4 + col * 4);
        float4 c1 = *reinterpret_cast<float4*>(colmax4 + (col + 1) * 4);
        float m0 = fmaxf(fmaxf(c0.x, c0.y), fmaxf(c0.z, c0.w));
        float m1 = fmaxf(fmaxf(c1.x, c1.y), fmaxf(c1.z, c1.w));
        acc[nt][0] = __expf(acc[nt][0] - m0);
        acc[nt][2] = __expf(acc[nt][2] - m0);
        acc[nt][1] = __expf(acc[nt][1] - m1);
        acc[nt][3] = __expf(acc[nt][3] - m1);
        sA[nt] = acc[nt][0] + acc[nt][2];
        sB[nt] = acc[nt][1] + acc[nt][3];
    }
#pragma unroll
    for (int off = 4; off < 32; off <<= 1) {
#pragma unroll
        for (int nt = 0; nt < 8; nt++) {
            sA[nt] += __shfl_xor_sync(0xffffffffu, sA[nt], off);
            sB[nt] += __shfl_xor_sync(0xffffffffu, sB[nt], off);
        }
    }
    if (g == 0) {
#pragma unroll
        for (int nt = 0; nt < 8; nt++) {
            const int col = nw * 64 + nt * 8 + tg * 2;
            colsum4[col * 4 + mw] = sA[nt];
            colsum4[(col + 1) * 4 + mw] = sB[nt];
        }
    }
    __syncthreads();

    unsigned char* asg8 = g_asg8 + (size_t)b * KK * HW;
    float rowsum = 0.f, rowsum8 = 0.f;
#pragma unroll
    for (int nt = 0; nt < 8; nt++) {
        const int col = nw * 64 + nt * 8 + tg * 2;
        float4 s0 = *reinterpret_cast<float4*>(colsum4 + col * 4);
        float4 s1 = *reinterpret_cast<float4*>(colsum4 + (col + 1) * 4);
        float inv0 = 1.f / (s0.x + s0.y + s0.z + s0.w);
        float inv1 = 1.f / (s1.x + s1.y + s1.z + s1.w);
        float a00 = acc[nt][0] * inv0, a01 = acc[nt][1] * inv1;
        float a02 = acc[nt][2] * inv0, a03 = acc[nt][3] * inv1;
        *reinterpret_cast<unsigned short*>(asg8 + (size_t)row * HW + i0 + col) =
            pack_e4m3x2(a00, a01);
        *reinterpret_cast<unsigned short*>(asg8 + (size_t)(row + 8) * HW + i0 + col) =
            pack_e4m3x2(a02, a03);
        rowsum  += a00 + a01;
        rowsum8 += a02 + a03;
    }
#pragma unroll
    for (int off = 1; off < 4; off <<= 1) {
        rowsum  += __shfl_xor_sync(0xffffffffu, rowsum, off);
        rowsum8 += __shfl_xor_sync(0xffffffffu, rowsum8, off);
    }
    if (tg == 0) {
        asum2[row * 2 + nw] = rowsum;
        asum2[(row + 8) * 2 + nw] = rowsum8;
    }
    __syncthreads();
    if (t < KK)
        g_asum_part[(b * KK + t) * 32 + bi] = asum2[t * 2] + asum2[t * 2 + 1];
}

// ---------------- K3: vlad GEMM, all-fp8 operands (split-K over i, i-chunk 32) ----
// grid (4 c2-tiles, NSPLIT, BB), 256 threads
__global__ __launch_bounds__(256) void k_vlad() {
    __shared__ __align__(16) unsigned smA[2 * 64 * AST2];    // assign fp8, [k][32B]
    __shared__ __align__(16) unsigned smXr[2 * 32 * XRST];   // raw x8, [i][128B]
    __shared__ __align__(16) unsigned smXt[128 * XTST];      // xn fp8 transposed, [c2][32B]
    __shared__ __half2 rnh2[128 * 4];                        // [c2][4] pairs of rn(i%8)

    const int c2b = blockIdx.x * 128;
    const int split = blockIdx.y;
    const int b = blockIdx.z;
    const int t = threadIdx.x;
    const int lane = t & 31, warp = t >> 5;
    const int mw = warp >> 1, nw = warp & 1;
    const int g = lane >> 2, tg = lane & 3;
    const int ib = t >> 5, cb = t & 31;      // transpose role
    const int row = mw * 16 + g;

    // fill rnh2: rn as half, paired by i%8 (2j, 2j+1)
#pragma unroll
    for (int p = 0; p < 2; p++) {
        int idx = t + 256 * p;
        int c2 = idx >> 2, j = idx & 3;
        float lo = g_rnorm[(size_t)b * HW + (2 * j) * 512 + c2b + c2];
        float hi = g_rnorm[(size_t)b * HW + (2 * j + 1) * 512 + c2b + c2];
        rnh2[idx] = __floats2half2_rn(lo, hi);
    }

    const unsigned char* asg8 = g_asg8 + (size_t)b * KK * HW;
    const unsigned char* x8b  = g_x8 + (size_t)b * HW * CC;

    const int ibase0 = split * (HW / NSPLIT);

    // prologue: chunk 0 into buffer 0
    if (t < 128)
        cpasync16(smA + (t >> 1) * AST2 + (t & 1) * 4,
                  asg8 + (size_t)(t >> 1) * HW + ibase0 + (t & 1) * 16);
    cpasync16(smXr + (t >> 3) * XRST + (t & 7) * 4,
              x8b + (size_t)(ibase0 + (t >> 3)) * 512 + c2b + (t & 7) * 16);
    cp_commit();
    cp_wait0();
    __syncthreads();

    // preload this thread's rn pairs (constant across iters)
    __half2 rnr0[4], rnr1[4];
#pragma unroll
    for (int c = 0; c < 4; c++) {
        rnr0[c] = rnh2[(4 * cb + c) * 4 + 2 * (ib & 1)];
        rnr1[c] = rnh2[(4 * cb + c) * 4 + 2 * (ib & 1) + 1];
    }

    float acc[8][4];
#pragma unroll
    for (int nt = 0; nt < 8; nt++)
#pragma unroll
        for (int q = 0; q < 4; q++) acc[nt][q] = 0.f;

    const int NIT = (HW / NSPLIT) / 32;
    for (int it = 0; it < NIT; it++) {
        const int s = it & 1, sn = s ^ 1;
        if (it < NIT - 1) {
            const int ibn = ibase0 + (it + 1) * 32;
            if (t < 128)
                cpasync16(smA + sn * (64 * AST2) + (t >> 1) * AST2 + (t & 1) * 4,
                          asg8 + (size_t)(t >> 1) * HW + ibn + (t & 1) * 16);
            cpasync16(smXr + sn * (32 * XRST) + (t >> 3) * XRST + (t & 7) * 4,
                      x8b + (size_t)(ibn + (t >> 3)) * 512 + c2b + (t & 7) * 16);
        }
        cp_commit();

        // transpose + rnorm-scale: smXr[s] ([i][c2]) -> smXt ([c2][i]), fp8
        {
            const unsigned* Xr = smXr + s * (32 * XRST);
            unsigned r0 = Xr[(4 * ib + 0) * XRST + cb];
            unsigned r1 = Xr[(4 * ib + 1) * XRST + cb];
            unsigned r2 = Xr[(4 * ib + 2) * XRST + cb];
            unsigned r3 = Xr[(4 * ib + 3) * XRST + cb];
#pragma unroll
            for (int c = 0; c < 4; c++) {
                const unsigned ctl = (unsigned)(c | ((c + 4) << 4));
                unsigned p01, p23;
                asm("prmt.b32 %0, %1, %2, %3;" : "=r"(p01) : "r"(r0), "r"(r1), "r"(ctl));
                asm("prmt.b32 %0, %1, %2, %3;" : "=r"(p23) : "r"(r2), "r"(r3), "r"(ctl));
                unsigned short s01 = (unsigned short)p01, s23 = (unsigned short)p23;
                unsigned h01u, h23u;
                asm("cvt.rn.f16x2.e4m3x2 %0, %1;" : "=r"(h01u) : "h"(s01));
                asm("cvt.rn.f16x2.e4m3x2 %0, %1;" : "=r"(h23u) : "h"(s23));
                __half2 h01 = __hmul2(*reinterpret_cast<__half2*>(&h01u), rnr0[c]);
                __half2 h23 = __hmul2(*reinterpret_cast<__half2*>(&h23u), rnr1[c]);
                unsigned short q01, q23;
                asm("cvt.rn.satfinite.e4m3x2.f16x2 %0, %1;"
                    : "=h"(q01) : "r"(*reinterpret_cast<unsigned*>(&h01)));
                asm("cvt.rn.satfinite.e4m3x2.f16x2 %0, %1;"
                    : "=h"(q23) : "r"(*reinterpret_cast<unsigned*>(&h23)));
                smXt[(4 * cb + c) * XTST + ib] = (unsigned)q01 | ((unsigned)q23 << 16);
            }
        }
        __syncthreads();   // smXt ready

        // fp8 MMA: k = 32 per instruction
        {
            const unsigned* As = smA + s * (64 * AST2);
            unsigned a0 = As[row * AST2 + tg];
            unsigned a1 = As[(row + 8) * AST2 + tg];
            unsigned a2 = As[row * AST2 + tg + 4];
            unsigned a3 = As[(row + 8) * AST2 + tg + 4];
#pragma unroll
            for (int nt = 0; nt < 8; nt++) {
                const int col = nw * 64 + nt * 8 + g;
                unsigned b0 = smXt[col * XTST + tg];
                unsigned b1 = smXt[col * XTST + tg + 4];
                mma16832fp8(acc[nt], a0, a1, a2, a3, b0, b1);
            }
        }
        cp_wait0();
        __syncthreads();   // next chunk landed; MMA done -> smXt reusable
    }

    // epilogue: write bf16 partials
    unsigned* vp = reinterpret_cast<unsigned*>(g_vpart) +
                   (((size_t)(split * BB + b)) * KK * CC >> 1);
#pragma unroll
    for (int nt = 0; nt < 8; nt++) {
        const int col = c2b + nw * 64 + nt * 8 + tg * 2;
        vp[((size_t)row * CC + col) >> 1]       = pack_bf2(acc[nt][0], acc[nt][1]);
        vp[((size_t)(row + 8) * CC + col) >> 1] = pack_bf2(acc[nt][2], acc[nt][3]);
    }
}

// ---------------- K4a: combine + intra-normalize ----------------
__global__ __launch_bounds__(128) void k_intra(const float* __restrict__ cent,
                                               float* __restrict__ out) {
    __shared__ float red[4];
    __shared__ float bcastA, bcastR;

    const int k = blockIdx.x, b = blockIdx.y;
    const int t = threadIdx.x;
    const int lane = t & 31, warp = t >> 5;

    if (warp == 0) {
        float s = g_asum_part[(b * KK + k) * 32 + lane];
#pragma unroll
        for (int o = 16; o > 0; o >>= 1) s += __shfl_down_sync(0xffffffffu, s, o);
        if (lane == 0) bcastA = s;
    }
    __syncthreads();
    const float as = bcastA;

    const size_t base = ((size_t)(b * KK + k)) * CC;
    const float4 cc = reinterpret_cast<const float4*>(cent + k * CC)[t];
    float4 v4 = make_float4(-as * cc.x, -as * cc.y, -as * cc.z, -as * cc.w);
    const unsigned* vp32 = reinterpret_cast<const unsigned*>(g_vpart);
#pragma unroll
    for (int s = 0; s < NSPLIT; s++) {
        uint2 u = *reinterpret_cast<const uint2*>(
            vp32 + (((size_t)s * BB * KK * CC + base) >> 1) + t * 2);
        float2 f0 = __bfloat1622float2(*reinterpret_cast<__nv_bfloat162*>(&u.x));
        float2 f1 = __bfloat1622float2(*reinterpret_cast<__nv_bfloat162*>(&u.y));
        v4.x += f0.x; v4.y += f0.y; v4.z += f1.x; v4.w += f1.y;
    }
    float ss = v4.x * v4.x + v4.y * v4.y + v4.z * v4.z + v4.w * v4.w;
#pragma unroll
    for (int o = 16; o > 0; o >>= 1) ss += __shfl_down_sync(0xffffffffu, ss, o);
    if (lane == 0) red[warp] = ss;
    __syncthreads();
    if (t == 0) {
        float tot = red[0] + red[1] + red[2] + red[3];
        float rinv = 1.f / fmaxf(sqrtf(tot), 1e-12f);
        bcastR = rinv;
        g_gss[b * KK + k] = tot * rinv * rinv;
    }
    __syncthreads();
    const float rinv = bcastR;
    float4 y;
    y.x = v4.x * rinv; y.y = v4.y * rinv; y.z = v4.z * rinv; y.w = v4.w * rinv;
    reinterpret_cast<float4*>(out + base)[t] = y;
}

// ---------------- K4b: global L2 normalize (parallel slices) ----------------
__global__ __launch_bounds__(256) void k_gnorm(float* __restrict__ out) {
    __shared__ float red[2];
    __shared__ float bcast;
    const int sl = blockIdx.x, b = blockIdx.y, t = threadIdx.x;
    const int lane = t & 31, warp = t >> 5;

    if (t < KK) {
        float s = g_gss[b * KK + t];
#pragma unroll
        for (int o = 16; o > 0; o >>= 1) s += __shfl_down_sync(0xffffffffu, s, o);
        if (lane == 0) red[warp] = s;
    }
    __syncthreads();
    if (t == 0) bcast = 1.f / fmaxf(sqrtf(red[0] + red[1]), 1e-12f);
    __syncthreads();
    const float gr = bcast;

    float4* ob = reinterpret_cast<float4*>(out + (size_t)b * KK * CC + sl * 4096);
#pragma unroll
    for (int u = 0; u < 4; u++) {
        float4 v = ob[u * 256 + t];
        v.x *= gr; v.y *= gr; v.z *= gr; v.w *= gr;
        ob[u * 256 + t] = v;
    }
}

// ---------------- launch ----------------
extern "C" void kernel_launch(void* const* d_in, const int* in_sizes, int n_in,
                              void* d_out, int out_size) {
    (void)in_sizes; (void)n_in; (void)out_size;
    const float* x    = (const float*)d_in[0];
    const float* w    = (const float*)d_in[1];
    const float* bias = (const float*)d_in[2];
    const float* cent = (const float*)d_in[3];
    float* out = (float*)d_out;

    k_pre<<<128, 256>>>(w);
    k_logits<<<dim3(HW / 128, BB), 256>>>(x, bias);
    k_vlad<<<dim3(4, NSPLIT, BB), 256>>>();
    k_intra<<<dim3(KK, BB), 128>>>(cent, out);
    k_gnorm<<<dim3(8, BB), 256>>>(out);
}

// round 16
// speedup vs baseline: 1.1951x; 1.1951x over previous
#include <cuda_runtime.h>
#include <cuda_bf16.h>
#include <math.h>

#define BB 64
#define CC 512
#define KK 64
#define HW 4096
#define NSPLIT 8

#define AST 20     // logits W tile stride (u32)
#define BST 136    // logits X tile stride (u32)
#define AST2 12    // vlad A fp8 tile stride (u32)
#define BST2 136   // vlad B fp8 tile stride (u32)

// ---- scratch (device globals; no allocation allowed) ----
__device__ __align__(16) __nv_bfloat16 g_wb[KK * CC];
__device__ __align__(16) float         g_rnorm[BB * HW];
__device__ __align__(16) unsigned char g_x8[(size_t)BB * 8 * 128 * 2048]; // [b][qq][c/4][c2*4B]
__device__ __align__(16) unsigned char g_a8[(size_t)BB * KK * HW];        // [b][k][i']
__device__ __align__(16) float         g_asum_part[BB * KK * 32];
__device__ __align__(16) __nv_bfloat16 g_vpart[(size_t)NSPLIT * BB * KK * CC];
__device__ __align__(16) float         g_gss[BB * KK];

__device__ __forceinline__ void mma16816(float* d, const unsigned* a, const unsigned* b) {
    asm volatile(
        "mma.sync.aligned.m16n8k16.row.col.f32.bf16.bf16.f32 "
        "{%0,%1,%2,%3}, {%4,%5,%6,%7}, {%8,%9}, {%0,%1,%2,%3};"
        : "+f"(d[0]), "+f"(d[1]), "+f"(d[2]), "+f"(d[3])
        : "r"(a[0]), "r"(a[1]), "r"(a[2]), "r"(a[3]), "r"(b[0]), "r"(b[1]));
}

__device__ __forceinline__ void mma16832fp8(float* d, unsigned a0, unsigned a1,
                                            unsigned a2, unsigned a3,
                                            unsigned b0, unsigned b1) {
    asm volatile(
        "mma.sync.aligned.m16n8k32.row.col.f32.e4m3.e4m3.f32 "
        "{%0,%1,%2,%3}, {%4,%5,%6,%7}, {%8,%9}, {%0,%1,%2,%3};"
        : "+f"(d[0]), "+f"(d[1]), "+f"(d[2]), "+f"(d[3])
        : "r"(a0), "r"(a1), "r"(a2), "r"(a3), "r"(b0), "r"(b1));
}

__device__ __forceinline__ unsigned pack_bf2(float lo, float hi) {
    __nv_bfloat162 p = __floats2bfloat162_rn(lo, hi);
    return *reinterpret_cast<unsigned*>(&p);
}
__device__ __forceinline__ unsigned short pack_e4m3x2(float lo, float hi) {
    unsigned short r;
    asm("cvt.rn.satfinite.e4m3x2.f32 %0, %1, %2;" : "=h"(r) : "f"(hi), "f"(lo));
    return r;
}

__device__ __forceinline__ void cpasync16(unsigned* smem, const void* gmem) {
    unsigned s = (unsigned)__cvta_generic_to_shared(smem);
    asm volatile("cp.async.ca.shared.global [%0], [%1], 16;\n" :: "r"(s), "l"(gmem));
}
__device__ __forceinline__ void cp_commit() { asm volatile("cp.async.commit_group;\n"); }
__device__ __forceinline__ void cp_wait0()  { asm volatile("cp.async.wait_group 0;\n"); }

// ---------------- K_pre ----------------
__global__ void k_pre(const float* __restrict__ w) {
    int t = blockIdx.x * 256 + threadIdx.x;
    if (t < KK * CC) g_wb[t] = __float2bfloat16(w[t]);
}

// ---------------- K2: norm + logits GEMM + softmax; emit x8 + a8 (permuted) ----
// grid (HW/128, BB), 256 threads, K-chunk = 32 channels
__global__ __launch_bounds__(256) void k_logits(const float* __restrict__ x,
                                                const float* __restrict__ conv_b) {
    __shared__ __align__(16) unsigned smW[2 * KK * AST];
    __shared__ __align__(16) unsigned smX[2 * 16 * BST];
    __shared__ float rnorm_s[128];
    __shared__ float bias_s[KK];

    const int b  = blockIdx.y;
    const int bi = blockIdx.x;
    const int i0 = bi * 128;
    const int qq  = bi >> 2;           // i&7 class of this tile
    const int c2b = (bi & 3) * 128;    // xf column base
    const int t  = threadIdx.x;
    const int lane = t & 31, warp = t >> 5;
    const int mw = warp >> 1, nw = warp & 1;
    const int g = lane >> 2, tg = lane & 3;

    if (t < KK) bias_s[t] = conv_b[t];

    const float* xb = x + (size_t)b * CC * HW + i0;
    const unsigned* wb32 = reinterpret_cast<const unsigned*>(g_wb);

    const int c4 = t & 31, cg = t >> 5;
    const int wrow = t >> 2, wq = t & 3;

    // x8 destination for this thread's (cg, c4) lane: row = cgroup, 16B at c2 = c2b+4c4
    unsigned char* x8dst = g_x8 + ((size_t)(b * 8 + qq) * 128) * 2048 + c2b * 4 + c4 * 16;

    float acc[8][4];
#pragma unroll
    for (int nt = 0; nt < 8; nt++)
#pragma unroll
        for (int q = 0; q < 4; q++) acc[nt][q] = 0.f;
    float4 ssq4 = make_float4(0.f, 0.f, 0.f, 0.f);

    float4 xr[4];
    cpasync16(smW + wrow * AST + wq * 4, wb32 + wrow * (CC / 2) + wq * 4);
    cp_commit();
#pragma unroll
    for (int r = 0; r < 4; r++)
        xr[r] = *reinterpret_cast<const float4*>(xb + (size_t)(4 * cg + r) * HW + c4 * 4);
    {
        ssq4.x += xr[0].x * xr[0].x + xr[1].x * xr[1].x + xr[2].x * xr[2].x + xr[3].x * xr[3].x;
        ssq4.y += xr[0].y * xr[0].y + xr[1].y * xr[1].y + xr[2].y * xr[2].y + xr[3].y * xr[3].y;
        ssq4.z += xr[0].z * xr[0].z + xr[1].z * xr[1].z + xr[2].z * xr[2].z + xr[3].z * xr[3].z;
        ssq4.w += xr[0].w * xr[0].w + xr[1].w * xr[1].w + xr[2].w * xr[2].w + xr[3].w * xr[3].w;
        uint4 p0 = make_uint4(pack_bf2(xr[0].x, xr[1].x), pack_bf2(xr[0].y, xr[1].y),
                              pack_bf2(xr[0].z, xr[1].z), pack_bf2(xr[0].w, xr[1].w));
        uint4 p1 = make_uint4(pack_bf2(xr[2].x, xr[3].x), pack_bf2(xr[2].y, xr[3].y),
                              pack_bf2(xr[2].z, xr[3].z), pack_bf2(xr[2].w, xr[3].w));
        *reinterpret_cast<uint4*>(smX + (2 * cg) * BST + c4 * 4) = p0;
        *reinterpret_cast<uint4*>(smX + (2 * cg + 1) * BST + c4 * 4) = p1;
        // fp8: u32 = channels (4cg..4cg+3) for one c2; uint4 = 4 consecutive c2
        unsigned px0 = (unsigned)pack_e4m3x2(xr[0].x, xr[1].x) |
                       ((unsigned)pack_e4m3x2(xr[2].x, xr[3].x) << 16);
        unsigned px1 = (unsigned)pack_e4m3x2(xr[0].y, xr[1].y) |
                       ((unsigned)pack_e4m3x2(xr[2].y, xr[3].y) << 16);
        unsigned px2 = (unsigned)pack_e4m3x2(xr[0].z, xr[1].z) |
                       ((unsigned)pack_e4m3x2(xr[2].z, xr[3].z) << 16);
        unsigned px3 = (unsigned)pack_e4m3x2(xr[0].w, xr[1].w) |
                       ((unsigned)pack_e4m3x2(xr[2].w, xr[3].w) << 16);
        *reinterpret_cast<uint4*>(x8dst + (size_t)cg * 2048) =
            make_uint4(px0, px1, px2, px3);
    }
    cp_wait0();
    __syncthreads();

    const int NIT = CC / 32;
    for (int it = 0; it < NIT; it++) {
        const int c1 = (it + 1) * 32;
        const int s = it & 1, sn = s ^ 1;
        if (it < NIT - 1) {
            cpasync16(smW + sn * (KK * AST) + wrow * AST + wq * 4,
                      wb32 + wrow * (CC / 2) + (c1 >> 1) + wq * 4);
            cp_commit();
#pragma unroll
            for (int r = 0; r < 4; r++)
                xr[r] = *reinterpret_cast<const float4*>(
                    xb + (size_t)(c1 + 4 * cg + r) * HW + c4 * 4);
        }

        const unsigned* Ws = smW + s * (KK * AST);
        const unsigned* Xs = smX + s * (16 * BST);
        const int row = mw * 16 + g;
#pragma unroll
        for (int ks = 0; ks < 2; ks++) {
            unsigned a[4];
            a[0] = Ws[row * AST + ks * 8 + tg];
            a[1] = Ws[(row + 8) * AST + ks * 8 + tg];
            a[2] = Ws[row * AST + ks * 8 + tg + 4];
            a[3] = Ws[(row + 8) * AST + ks * 8 + tg + 4];
#pragma unroll
            for (int nt = 0; nt < 8; nt++) {
                const int col = nw * 64 + nt * 8 + g;
                unsigned bf[2];
                bf[0] = Xs[(ks * 8 + tg) * BST + col];
                bf[1] = Xs[(ks * 8 + tg + 4) * BST + col];
                mma16816(acc[nt], a, bf);
            }
        }

        if (it < NIT - 1) {
            unsigned* Xn = smX + sn * (16 * BST);
            ssq4.x += xr[0].x * xr[0].x + xr[1].x * xr[1].x + xr[2].x * xr[2].x + xr[3].x * xr[3].x;
            ssq4.y += xr[0].y * xr[0].y + xr[1].y * xr[1].y + xr[2].y * xr[2].y + xr[3].y * xr[3].y;
            ssq4.z += xr[0].z * xr[0].z + xr[1].z * xr[1].z + xr[2].z * xr[2].z + xr[3].z * xr[3].z;
            ssq4.w += xr[0].w * xr[0].w + xr[1].w * xr[1].w + xr[2].w * xr[2].w + xr[3].w * xr[3].w;
            uint4 p0 = make_uint4(pack_bf2(xr[0].x, xr[1].x), pack_bf2(xr[0].y, xr[1].y),
                                  pack_bf2(xr[0].z, xr[1].z), pack_bf2(xr[0].w, xr[1].w));
            uint4 p1 = make_uint4(pack_bf2(xr[2].x, xr[3].x), pack_bf2(xr[2].y, xr[3].y),
                                  pack_bf2(xr[2].z, xr[3].z), pack_bf2(xr[2].w, xr[3].w));
            *reinterpret_cast<uint4*>(Xn + (2 * cg) * BST + c4 * 4) = p0;
            *reinterpret_cast<uint4*>(Xn + (2 * cg + 1) * BST + c4 * 4) = p1;
            unsigned px0 = (unsigned)pack_e4m3x2(xr[0].x, xr[1].x) |
                           ((unsigned)pack_e4m3x2(xr[2].x, xr[3].x) << 16);
            unsigned px1 = (unsigned)pack_e4m3x2(xr[0].y, xr[1].y) |
                           ((unsigned)pack_e4m3x2(xr[2].y, xr[3].y) << 16);
            unsigned px2 = (unsigned)pack_e4m3x2(xr[0].z, xr[1].z) |
                           ((unsigned)pack_e4m3x2(xr[2].z, xr[3].z) << 16);
            unsigned px3 = (unsigned)pack_e4m3x2(xr[0].w, xr[1].w) |
                           ((unsigned)pack_e4m3x2(xr[2].w, xr[3].w) << 16);
            *reinterpret_cast<uint4*>(x8dst + (size_t)(it * 8 + 8 + cg) * 2048) =
                make_uint4(px0, px1, px2, px3);
        }
        cp_wait0();
        __syncthreads();
    }

    // ---- ssq -> rnorm ----
    float4* ssq_sm = reinterpret_cast<float4*>(smW);
    ssq_sm[cg * 32 + c4] = ssq4;
    __syncthreads();
    if (t < 32) {
        float4 s = ssq_sm[t];
#pragma unroll
        for (int r = 1; r < 8; r++) {
            float4 u = ssq_sm[r * 32 + t];
            s.x += u.x; s.y += u.y; s.z += u.z; s.w += u.w;
        }
        float4 rn;
        rn.x = 1.f / fmaxf(sqrtf(s.x), 1e-12f);
        rn.y = 1.f / fmaxf(sqrtf(s.y), 1e-12f);
        rn.z = 1.f / fmaxf(sqrtf(s.z), 1e-12f);
        rn.w = 1.f / fmaxf(sqrtf(s.w), 1e-12f);
        reinterpret_cast<float4*>(rnorm_s)[t] = rn;
        *reinterpret_cast<float4*>(g_rnorm + (size_t)b * HW + i0 + t * 4) = rn;
    }
    __syncthreads();

    float* colmax4 = reinterpret_cast<float*>(smX);          // [128][4]
    float* colsum4 = reinterpret_cast<float*>(smX) + 512;    // [128][4]
    float* asum2   = reinterpret_cast<float*>(smX) + 1024;   // [64][2]
    unsigned char* Av8 = reinterpret_cast<unsigned char*>(smX) + 8192;  // [64][128]

    const int row = mw * 16 + g;
    const float b0v = bias_s[row], b1v = bias_s[row + 8];

#pragma unroll
    for (int nt = 0; nt < 8; nt++) {
        const int col = nw * 64 + nt * 8 + tg * 2;
        const float r0 = rnorm_s[col], r1 = rnorm_s[col + 1];
        acc[nt][0] = acc[nt][0] * r0 + b0v;
        acc[nt][1] = acc[nt][1] * r1 + b0v;
        acc[nt][2] = acc[nt][2] * r0 + b1v;
        acc[nt][3] = acc[nt][3] * r1 + b1v;
    }

    float mA[8], mB[8];
#pragma unroll
    for (int nt = 0; nt < 8; nt++) {
        mA[nt] = fmaxf(acc[nt][0], acc[nt][2]);
        mB[nt] = fmaxf(acc[nt][1], acc[nt][3]);
    }
#pragma unroll
    for (int off = 4; off < 32; off <<= 1) {
#pragma unroll
        for (int nt = 0; nt < 8; nt++) {
            mA[nt] = fmaxf(mA[nt], __shfl_xor_sync(0xffffffffu, mA[nt], off));
            mB[nt] = fmaxf(mB[nt], __shfl_xor_sync(0xffffffffu, mB[nt], off));
        }
    }
    if (g == 0) {
#pragma unroll
        for (int nt = 0; nt < 8; nt++) {
            const int col = nw * 64 + nt * 8 + tg * 2;
            colmax4[col * 4 + mw] = mA[nt];
            colmax4[(col + 1) * 4 + mw] = mB[nt];
        }
    }
    __syncthreads();

    float sA[8], sB[8];
#pragma unroll
    for (int nt = 0; nt < 8; nt++) {
        const int col = nw * 64 + nt * 8 + tg * 2;
        float4 c0 = *reinterpret_cast<float4*>(colmax4 + col * 4);
        float4 c1 = *reinterpret_cast<float4*>(colmax4 + (col + 1) * 4);
        float m0 = fmaxf(fmaxf(c0.x, c0.y), fmaxf(c0.z, c0.w));
        float m1 = fmaxf(fmaxf(c1.x, c1.y), fmaxf(c1.z, c1.w));
        acc[nt][0] = __expf(acc[nt][0] - m0);
        acc[nt][2] = __expf(acc[nt][2] - m0);
        acc[nt][1] = __expf(acc[nt][1] - m1);
        acc[nt][3] = __expf(acc[nt][3] - m1);
        sA[nt] = acc[nt][0] + acc[nt][2];
        sB[nt] = acc[nt][1] + acc[nt][3];
    }
#pragma unroll
    for (int off = 4; off < 32; off <<= 1) {
#pragma unroll
        for (int nt = 0; nt < 8; nt++) {
            sA[nt] += __shfl_xor_sync(0xffffffffu, sA[nt], off);
            sB[nt] += __shfl_xor_sync(0xffffffffu, sB[nt], off);
        }
    }
    if (g == 0) {
#pragma unroll
        for (int nt = 0; nt < 8; nt++) {
            const int col = nw * 64 + nt * 8 + tg * 2;
            colsum4[col * 4 + mw] = sA[nt];
            colsum4[(col + 1) * 4 + mw] = sB[nt];
        }
    }
    __syncthreads();

    float rowsum = 0.f, rowsum8 = 0.f;
#pragma unroll
    for (int nt = 0; nt < 8; nt++) {
        const int col = nw * 64 + nt * 8 + tg * 2;
        float4 s0 = *reinterpret_cast<float4*>(colsum4 + col * 4);
        float4 s1 = *reinterpret_cast<float4*>(colsum4 + (col + 1) * 4);
        float inv0 = 1.f / (s0.x + s0.y + s0.z + s0.w);
        float inv1 = 1.f / (s1.x + s1.y + s1.z + s1.w);
        float a00 = acc[nt][0] * inv0, a01 = acc[nt][1] * inv1;
        float a02 = acc[nt][2] * inv0, a03 = acc[nt][3] * inv1;
        *reinterpret_cast<unsigned short*>(Av8 + row * 128 + col) = pack_e4m3x2(a00, a01);
        *reinterpret_cast<unsigned short*>(Av8 + (row + 8) * 128 + col) = pack_e4m3x2(a02, a03);
        rowsum  += a00 + a01;
        rowsum8 += a02 + a03;
    }
#pragma unroll
    for (int off = 1; off < 4; off <<= 1) {
        rowsum  += __shfl_xor_sync(0xffffffffu, rowsum, off);
        rowsum8 += __shfl_xor_sync(0xffffffffu, rowsum8, off);
    }
    if (tg == 0) {
        asum2[row * 2 + nw] = rowsum;
        asum2[(row + 8) * 2 + nw] = rowsum8;
    }
    __syncthreads();

    // permuted coalesced a8 write: i' = q7*512 + bi*16 + m, m = col>>3, q7 = col&7
#pragma unroll
    for (int p = 0; p < 2; p++) {
        const int u = t + 256 * p;
        const int k = u >> 3, q7 = u & 7;
        unsigned vv[4];
#pragma unroll
        for (int w4 = 0; w4 < 4; w4++) {
            unsigned r = 0;
#pragma unroll
            for (int bt = 0; bt < 4; bt++)
                r |= (unsigned)Av8[k * 128 + 8 * (w4 * 4 + bt) + q7] << (8 * bt);
            vv[w4] = r;
        }
        *reinterpret_cast<uint4*>(g_a8 + ((size_t)b * KK + k) * HW + q7 * 512 + bi * 16) =
            make_uint4(vv[0], vv[1], vv[2], vv[3]);
    }
    if (t < KK)
        g_asum_part[(b * KK + t) * 32 + bi] = asum2[t * 2] + asum2[t * 2 + 1];
}

// ---------------- K3: vlad fp8 GEMM, permuted K (split = qq), zero conversion ----
// grid (4 c2-tiles, 8 qq, BB), 256 threads; K per block = 512 (channels)
__global__ __launch_bounds__(256) void k_vlad() {
    __shared__ __align__(16) unsigned smA[2 * KK * AST2];
    __shared__ __align__(16) unsigned smX[2 * 8 * BST2];
    __shared__ float rn_s[128];

    const int c2b = blockIdx.x * 128;
    const int qq = blockIdx.y;
    const int b = blockIdx.z;
    const int t = threadIdx.x;
    const int lane = t & 31, warp = t >> 5;
    const int mw = warp >> 1, nw = warp & 1;
    const int g = lane >> 2, tg = lane & 3;
    const int row = mw * 16 + g;

    if (t < 128) rn_s[t] = g_rnorm[(size_t)b * HW + qq * 512 + c2b + t];

    const unsigned char* a8 = g_a8 + (size_t)b * KK * HW + qq * 512;   // [k][c], row stride HW
    const unsigned char* x8 = g_x8 + ((size_t)(b * 8 + qq) * 128) * 2048 + c2b * 4;

    // prologue: chunk 0
    if (t < 128)
        cpasync16(smA + (t >> 1) * AST2 + (t & 1) * 4,
                  a8 + (size_t)(t >> 1) * HW + (t & 1) * 16);
    cpasync16(smX + (t >> 5) * BST2 + (t & 31) * 4,
              x8 + (size_t)(t >> 5) * 2048 + (t & 31) * 16);
    cp_commit();

    float acc[8][4];
#pragma unroll
    for (int nt = 0; nt < 8; nt++)
#pragma unroll
        for (int q = 0; q < 4; q++) acc[nt][q] = 0.f;

    cp_wait0();
    __syncthreads();

    const int NIT = 16;                 // 512 channels / 32 per chunk
    for (int it = 0; it < NIT; it++) {
        const int s = it & 1, sn = s ^ 1;
        if (it < NIT - 1) {
            const int c1 = (it + 1) * 32;
            if (t < 128)
                cpasync16(smA + sn * (KK * AST2) + (t >> 1) * AST2 + (t & 1) * 4,
                          a8 + (size_t)(t >> 1) * HW + c1 + (t & 1) * 16);
            cpasync16(smX + sn * (8 * BST2) + (t >> 5) * BST2 + (t & 31) * 4,
                      x8 + (size_t)((c1 >> 2) + (t >> 5)) * 2048 + (t & 31) * 16);
        }
        cp_commit();

        const unsigned* As = smA + s * (KK * AST2);
        const unsigned* Xs = smX + s * (8 * BST2);
        unsigned a0 = As[row * AST2 + tg];
        unsigned a1 = As[(row + 8) * AST2 + tg];
        unsigned a2 = As[row * AST2 + tg + 4];
        unsigned a3 = As[(row + 8) * AST2 + tg + 4];
#pragma unroll
        for (int nt = 0; nt < 8; nt++) {
            const int col = nw * 64 + nt * 8 + g;
            unsigned b0 = Xs[tg * BST2 + col];
            unsigned b1 = Xs[(tg + 4) * BST2 + col];
            mma16832fp8(acc[nt], a0, a1, a2, a3, b0, b1);
        }
        cp_wait0();
        __syncthreads();
    }

    // epilogue: scale by rnorm[qq*512 + c2] (column-wise), write bf16 partials
    unsigned* vp = reinterpret_cast<unsigned*>(g_vpart) +
                   (((size_t)(qq * BB + b)) * KK * CC >> 1);
#pragma unroll
    for (int nt = 0; nt < 8; nt++) {
        const int col = nw * 64 + nt * 8 + tg * 2;
        const float r0 = rn_s[col], r1 = rn_s[col + 1];
        vp[((size_t)row * CC + c2b + col) >> 1] =
            pack_bf2(acc[nt][0] * r0, acc[nt][1] * r1);
        vp[((size_t)(row + 8) * CC + c2b + col) >> 1] =
            pack_bf2(acc[nt][2] * r0, acc[nt][3] * r1);
    }
}

// ---------------- K4a: combine + intra-normalize ----------------
__global__ __launch_bounds__(128) void k_intra(const float* __restrict__ cent,
                                               float* __restrict__ out) {
    __shared__ float red[4];
    __shared__ float bcastA, bcastR;

    const int k = blockIdx.x, b = blockIdx.y;
    const int t = threadIdx.x;
    const int lane = t & 31, warp = t >> 5;

    if (warp == 0) {
        float s = g_asum_part[(b * KK + k) * 32 + lane];
#pragma unroll
        for (int o = 16; o > 0; o >>= 1) s += __shfl_down_sync(0xffffffffu, s, o);
        if (lane == 0) bcastA = s;
    }
    __syncthreads();
    const float as = bcastA;

    const size_t base = ((size_t)(b * KK + k)) * CC;
    const float4 cc = reinterpret_cast<const float4*>(cent + k * CC)[t];
    float4 v4 = make_float4(-as * cc.x, -as * cc.y, -as * cc.z, -as * cc.w);
    const unsigned* vp32 = reinterpret_cast<const unsigned*>(g_vpart);
#pragma unroll
    for (int s = 0; s < NSPLIT; s++) {
        uint2 u = *reinterpret_cast<const uint2*>(
            vp32 + (((size_t)s * BB * KK * CC + base) >> 1) + t * 2);
        float2 f0 = __bfloat1622float2(*reinterpret_cast<__nv_bfloat162*>(&u.x));
        float2 f1 = __bfloat1622float2(*reinterpret_cast<__nv_bfloat162*>(&u.y));
        v4.x += f0.x; v4.y += f0.y; v4.z += f1.x; v4.w += f1.y;
    }
    float ss = v4.x * v4.x + v4.y * v4.y + v4.z * v4.z + v4.w * v4.w;
#pragma unroll
    for (int o = 16; o > 0; o >>= 1) ss += __shfl_down_sync(0xffffffffu, ss, o);
    if (lane == 0) red[warp] = ss;
    __syncthreads();
    if (t == 0) {
        float tot = red[0] + red[1] + red[2] + red[3];
        float rinv = 1.f / fmaxf(sqrtf(tot), 1e-12f);
        bcastR = rinv;
        g_gss[b * KK + k] = tot * rinv * rinv;
    }
    __syncthreads();
    const float rinv = bcastR;
    float4 y;
    y.x = v4.x * rinv; y.y = v4.y * rinv; y.z = v4.z * rinv; y.w = v4.w * rinv;
    reinterpret_cast<float4*>(out + base)[t] = y;
}

// ---------------- K4b: global L2 normalize (parallel slices) ----------------
__global__ __launch_bounds__(256) void k_gnorm(float* __restrict__ out) {
    __shared__ float red[2];
    __shared__ float bcast;
    const int sl = blockIdx.x, b = blockIdx.y, t = threadIdx.x;
    const int lane = t & 31, warp = t >> 5;

    if (t < KK) {
        float s = g_gss[b * KK + t];
#pragma unroll
        for (int o = 16; o > 0; o >>= 1) s += __shfl_down_sync(0xffffffffu, s, o);
        if (lane == 0) red[warp] = s;
    }
    __syncthreads();
    if (t == 0) bcast = 1.f / fmaxf(sqrtf(red[0] + red[1]), 1e-12f);
    __syncthreads();
    const float gr = bcast;

    float4* ob = reinterpret_cast<float4*>(out + (size_t)b * KK * CC + sl * 4096);
#pragma unroll
    for (int u = 0; u < 4; u++) {
        float4 v = ob[u * 256 + t];
        v.x *= gr; v.y *= gr; v.z *= gr; v.w *= gr;
        ob[u * 256 + t] = v;
    }
}

// ---------------- launch ----------------
extern "C" void kernel_launch(void* const* d_in, const int* in_sizes, int n_in,
                              void* d_out, int out_size) {
    (void)in_sizes; (void)n_in; (void)out_size;
    const float* x    = (const float*)d_in[0];
    const float* w    = (const float*)d_in[1];
    const float* bias = (const float*)d_in[2];
    const float* cent = (const float*)d_in[3];
    float* out = (float*)d_out;

    k_pre<<<128, 256>>>(w);
    k_logits<<<dim3(HW / 128, BB), 256>>>(x, bias);
    k_vlad<<<dim3(4, NSPLIT, BB), 256>>>();
    k_intra<<<dim3(KK, BB), 128>>>(cent, out);
    k_gnorm<<<dim3(8, BB), 256>>>(out);
}